// round 5
// baseline (speedup 1.0000x reference)
#include <cuda_runtime.h>
#include <cstdint>

#define N_NODES 100000
#define N_EDGES 1600000
#define IN_F    512
#define OUT_F   64

// Scratch (allocation-free rule: __device__ globals)
__device__ float  g_h[(size_t)N_NODES * OUT_F];   // projected features
__device__ float  g_deg[N_NODES];                 // in-degree per dst node
__device__ float2 g_Wsp[IN_F * OUT_F];            // pre-split W: {big, small}

// ---------------------------------------------------------------------------
// tf32 helpers
// ---------------------------------------------------------------------------
__device__ __forceinline__ float2 split_tf32(float x) {
    unsigned b, s;
    asm("cvt.rna.tf32.f32 %0, %1;" : "=r"(b) : "f"(x));
    float r = x - __uint_as_float(b);
    asm("cvt.rna.tf32.f32 %0, %1;" : "=r"(s) : "f"(r));
    return make_float2(__uint_as_float(b), __uint_as_float(s));
}

__device__ __forceinline__ void mma8(float& d0, float& d1, float& d2, float& d3,
                                     float a0, float a1, float a2, float a3,
                                     float b0, float b1) {
    asm volatile("mma.sync.aligned.m16n8k8.row.col.f32.tf32.tf32.f32 "
                 "{%0,%1,%2,%3},{%4,%5,%6,%7},{%8,%9},{%0,%1,%2,%3};"
                 : "+f"(d0), "+f"(d1), "+f"(d2), "+f"(d3)
                 : "r"(__float_as_uint(a0)), "r"(__float_as_uint(a1)),
                   "r"(__float_as_uint(a2)), "r"(__float_as_uint(a3)),
                   "r"(__float_as_uint(b0)), "r"(__float_as_uint(b1)));
}

// ---------------------------------------------------------------------------
// 0) zero output accumulator + degree counters
// ---------------------------------------------------------------------------
__global__ void zero_kernel(float4* __restrict__ out4) {
    int i = blockIdx.x * blockDim.x + threadIdx.x;
    if (i < N_NODES * OUT_F / 4) out4[i] = make_float4(0.f, 0.f, 0.f, 0.f);
    if (i < N_NODES) g_deg[i] = 0.0f;
}

// ---------------------------------------------------------------------------
// 0b) pre-split W (512x64) into {big, small} pairs
// ---------------------------------------------------------------------------
__global__ void wsplit_kernel(const float* __restrict__ W) {
    int i = blockIdx.x * blockDim.x + threadIdx.x;
    if (i < IN_F * OUT_F) g_Wsp[i] = split_tf32(W[i]);
}

// ---------------------------------------------------------------------------
// 1) GEMM (tf32 tensor cores, 3xTF32): g_h = feat @ W
//    Block 128x64, 8 warps (4m x 2n), warp tile 32x32, KC=32.
//    smem holds pre-split {big,small} pairs; inner loop = LDS.64 + HMMA only.
// ---------------------------------------------------------------------------
#define AS_PAD 37
#define BS_PAD 66
#define SMEM_BYTES ((128 * AS_PAD + 32 * BS_PAD) * (int)sizeof(float2))

__global__ __launch_bounds__(256) void gemm_tf32_kernel(
    const float* __restrict__ feat)
{
    extern __shared__ float2 sm[];
    float2* As2 = sm;                      // [128][AS_PAD]
    float2* Bs2 = sm + 128 * AS_PAD;       // [32][BS_PAD]

    const int tid  = threadIdx.x;
    const int wid  = tid >> 5;
    const int lane = tid & 31;
    const int wm   = wid >> 1;      // 0..3
    const int wn   = wid & 1;       // 0..1
    const int gid  = lane >> 2;     // 0..7
    const int tig  = lane & 3;      // 0..3
    const int m0   = blockIdx.x * 128;

    float acc[2][4][4] = {};

    // A loader mapping: 128 rows x 8 float4-chunks, 4 chunks/thread
    const int lr = tid >> 1;                 // base pattern below uses i>>3
    (void)lr;

    float4 ra[4];   // A prefetch regs
    float4 rb[4];   // B prefetch regs (float2 pairs as float4)

    // prologue: load k0 = 0
    {
        #pragma unroll
        for (int q = 0; q < 4; q++) {
            const int i = tid + q * 256;      // 0..1023
            const int r = i >> 3;
            const int c4 = (i & 7) * 4;
            ra[q] = make_float4(0.f, 0.f, 0.f, 0.f);
            if (m0 + r < N_NODES)
                ra[q] = *reinterpret_cast<const float4*>(feat + (size_t)(m0 + r) * IN_F + c4);
        }
        #pragma unroll
        for (int q = 0; q < 4; q++) {
            const int j = tid + q * 256;      // float4 index over 1024 (=2048 float2)
            rb[q] = *reinterpret_cast<const float4*>(
                reinterpret_cast<const float*>(g_Wsp) + j * 4);  // pairs (k,n): p=j*2
        }
    }

    for (int k0 = 0; k0 < IN_F; k0 += 32) {
        // store current tile (split A, copy pre-split B)
        #pragma unroll
        for (int q = 0; q < 4; q++) {
            const int i = tid + q * 256;
            const int r = i >> 3;
            const int c4 = (i & 7) * 4;
            As2[r * AS_PAD + c4 + 0] = split_tf32(ra[q].x);
            As2[r * AS_PAD + c4 + 1] = split_tf32(ra[q].y);
            As2[r * AS_PAD + c4 + 2] = split_tf32(ra[q].z);
            As2[r * AS_PAD + c4 + 3] = split_tf32(ra[q].w);
        }
        #pragma unroll
        for (int q = 0; q < 4; q++) {
            const int j = tid + q * 256;
            const int p = j * 2;              // float2 pair index
            const int kk = p >> 6;            // 0..31
            const int nn = p & 63;            // even
            *reinterpret_cast<float4*>(&Bs2[kk * BS_PAD + nn]) = rb[q];
        }
        __syncthreads();

        // prefetch next tile
        const int kn = k0 + 32;
        if (kn < IN_F) {
            #pragma unroll
            for (int q = 0; q < 4; q++) {
                const int i = tid + q * 256;
                const int r = i >> 3;
                const int c4 = (i & 7) * 4;
                ra[q] = make_float4(0.f, 0.f, 0.f, 0.f);
                if (m0 + r < N_NODES)
                    ra[q] = *reinterpret_cast<const float4*>(feat + (size_t)(m0 + r) * IN_F + kn + c4);
            }
            #pragma unroll
            for (int q = 0; q < 4; q++) {
                const int j = tid + q * 256;
                rb[q] = *reinterpret_cast<const float4*>(
                    reinterpret_cast<const float*>(g_Wsp) + (size_t)kn * OUT_F * 2 + j * 4);
            }
        }

        // compute
        #pragma unroll
        for (int kf = 0; kf < 4; kf++) {
            float2 fa[2][4];
            #pragma unroll
            for (int mf = 0; mf < 2; mf++) {
                const int r = wm * 32 + mf * 16 + gid;
                const int c = kf * 8 + tig;
                fa[mf][0] = As2[r * AS_PAD + c];
                fa[mf][1] = As2[(r + 8) * AS_PAD + c];
                fa[mf][2] = As2[r * AS_PAD + c + 4];
                fa[mf][3] = As2[(r + 8) * AS_PAD + c + 4];
            }
            float2 fb[4][2];
            #pragma unroll
            for (int nf = 0; nf < 4; nf++) {
                const int c = wn * 32 + nf * 8 + gid;
                const int r = kf * 8 + tig;
                fb[nf][0] = Bs2[r * BS_PAD + c];
                fb[nf][1] = Bs2[(r + 4) * BS_PAD + c];
            }
            #pragma unroll
            for (int mf = 0; mf < 2; mf++)
                #pragma unroll
                for (int nf = 0; nf < 4; nf++) {
                    float* d = acc[mf][nf];
                    mma8(d[0], d[1], d[2], d[3],
                         fa[mf][0].x, fa[mf][1].x, fa[mf][2].x, fa[mf][3].x,
                         fb[nf][0].x, fb[nf][1].x);                      // big·big
                    mma8(d[0], d[1], d[2], d[3],
                         fa[mf][0].x, fa[mf][1].x, fa[mf][2].x, fa[mf][3].x,
                         fb[nf][0].y, fb[nf][1].y);                      // big·small
                    mma8(d[0], d[1], d[2], d[3],
                         fa[mf][0].y, fa[mf][1].y, fa[mf][2].y, fa[mf][3].y,
                         fb[nf][0].x, fb[nf][1].x);                      // small·big
                }
        }
        __syncthreads();
    }

    // epilogue
    #pragma unroll
    for (int mf = 0; mf < 2; mf++) {
        #pragma unroll
        for (int nf = 0; nf < 4; nf++) {
            const int c  = wn * 32 + nf * 8 + tig * 2;
            const int r0 = m0 + wm * 32 + mf * 16 + gid;
            if (r0 < N_NODES)
                *reinterpret_cast<float2*>(g_h + (size_t)r0 * OUT_F + c) =
                    make_float2(acc[mf][nf][0], acc[mf][nf][1]);
            if (r0 + 8 < N_NODES)
                *reinterpret_cast<float2*>(g_h + (size_t)(r0 + 8) * OUT_F + c) =
                    make_float2(acc[mf][nf][2], acc[mf][nf][3]);
        }
    }
}

// ---------------------------------------------------------------------------
// 2) Edge scatter: out[dst] += h[src] * w via red.global.add.v4.f32
// ---------------------------------------------------------------------------
__global__ __launch_bounds__(256) void edge_kernel(
    const int* __restrict__ src, const int* __restrict__ dst,
    const float* __restrict__ ew, float* __restrict__ out)
{
    const long long t = (long long)blockIdx.x * blockDim.x + threadIdx.x;
    const int e = (int)(t >> 4);
    const int l = (int)(t & 15);
    if (e >= N_EDGES) return;

    const int s = __ldg(src + e);
    const int d = __ldg(dst + e);
    const float w = __ldg(ew + e);

    float4 v = *reinterpret_cast<const float4*>(g_h + (size_t)s * OUT_F + l * 4);
    v.x *= w; v.y *= w; v.z *= w; v.w *= w;

    float* p = out + (size_t)d * OUT_F + l * 4;
    asm volatile("red.global.add.v4.f32 [%0], {%1,%2,%3,%4};"
                 :: "l"(p), "f"(v.x), "f"(v.y), "f"(v.z), "f"(v.w)
                 : "memory");

    if (l == 0) atomicAdd(&g_deg[d], 1.0f);
}

// ---------------------------------------------------------------------------
// 3) finalize (vectorized): out = relu( msum * (deg>0 ? 1/deg : 0) + bias )
// ---------------------------------------------------------------------------
__global__ void finalize_kernel(float4* __restrict__ out4, const float* __restrict__ bias) {
    const int i = blockIdx.x * blockDim.x + threadIdx.x;
    if (i >= N_NODES * OUT_F / 4) return;
    const int node = i >> 4;
    const int c4   = (i & 15) * 4;
    const float d  = g_deg[node];
    const float rinv = (d > 0.0f) ? (1.0f / d) : 0.0f;
    float4 v = out4[i];
    v.x = fmaxf(fmaf(v.x, rinv, __ldg(bias + c4 + 0)), 0.0f);
    v.y = fmaxf(fmaf(v.y, rinv, __ldg(bias + c4 + 1)), 0.0f);
    v.z = fmaxf(fmaf(v.z, rinv, __ldg(bias + c4 + 2)), 0.0f);
    v.w = fmaxf(fmaf(v.w, rinv, __ldg(bias + c4 + 3)), 0.0f);
    out4[i] = v;
}

// ---------------------------------------------------------------------------
extern "C" void kernel_launch(void* const* d_in, const int* in_sizes, int n_in,
                              void* d_out, int out_size)
{
    const float* feat     = (const float*)d_in[0];
    const float* edge_w   = (const float*)d_in[1];
    const float* weight   = (const float*)d_in[2];
    const float* bias     = (const float*)d_in[3];
    const int*   edge_src = (const int*)d_in[4];
    const int*   edge_dst = (const int*)d_in[5];
    float* out = (float*)d_out;

    cudaFuncSetAttribute(gemm_tf32_kernel,
                         cudaFuncAttributeMaxDynamicSharedMemorySize, SMEM_BYTES);

    zero_kernel<<<(N_NODES * OUT_F / 4 + 255) / 256, 256>>>((float4*)out);
    wsplit_kernel<<<(IN_F * OUT_F + 255) / 256, 256>>>(weight);
    gemm_tf32_kernel<<<(N_NODES + 127) / 128, 256, SMEM_BYTES>>>(feat);
    edge_kernel<<<(int)(((long long)N_EDGES * 16 + 255) / 256), 256>>>(edge_src, edge_dst, edge_w, out);
    finalize_kernel<<<(N_NODES * OUT_F / 4 + 255) / 256, 256>>>((float4*)out, bias);
}

// round 7
// speedup vs baseline: 1.0614x; 1.0614x over previous
#include <cuda_runtime.h>
#include <cstdint>

#define N_NODES 100000
#define N_EDGES 1600000
#define IN_F    512
#define OUT_F   64

// Scratch (allocation-free rule: __device__ globals)
__device__ float  g_h[(size_t)N_NODES * OUT_F];   // projected features
__device__ float  g_deg[N_NODES];                 // in-degree per dst node
__device__ float2 g_Wsp[IN_F * OUT_F];            // pre-split W: {big, small}

// ---------------------------------------------------------------------------
// tf32 helpers
// ---------------------------------------------------------------------------
__device__ __forceinline__ float2 split_tf32(float x) {
    unsigned b, s;
    asm("cvt.rna.tf32.f32 %0, %1;" : "=r"(b) : "f"(x));
    float r = x - __uint_as_float(b);
    asm("cvt.rna.tf32.f32 %0, %1;" : "=r"(s) : "f"(r));
    return make_float2(__uint_as_float(b), __uint_as_float(s));
}

__device__ __forceinline__ void mma8(float& d0, float& d1, float& d2, float& d3,
                                     float a0, float a1, float a2, float a3,
                                     float b0, float b1) {
    asm volatile("mma.sync.aligned.m16n8k8.row.col.f32.tf32.tf32.f32 "
                 "{%0,%1,%2,%3},{%4,%5,%6,%7},{%8,%9},{%0,%1,%2,%3};"
                 : "+f"(d0), "+f"(d1), "+f"(d2), "+f"(d3)
                 : "r"(__float_as_uint(a0)), "r"(__float_as_uint(a1)),
                   "r"(__float_as_uint(a2)), "r"(__float_as_uint(a3)),
                   "r"(__float_as_uint(b0)), "r"(__float_as_uint(b1)));
}

// ---------------------------------------------------------------------------
// 0) zero output accumulator + degree counters
// ---------------------------------------------------------------------------
__global__ void zero_kernel(float4* __restrict__ out4) {
    int i = blockIdx.x * blockDim.x + threadIdx.x;
    if (i < N_NODES * OUT_F / 4) out4[i] = make_float4(0.f, 0.f, 0.f, 0.f);
    if (i < N_NODES) g_deg[i] = 0.0f;
}

// ---------------------------------------------------------------------------
// 0b) pre-split W (512x64) into {big, small} pairs
// ---------------------------------------------------------------------------
__global__ void wsplit_kernel(const float* __restrict__ W) {
    int i = blockIdx.x * blockDim.x + threadIdx.x;
    if (i < IN_F * OUT_F) g_Wsp[i] = split_tf32(W[i]);
}

// ---------------------------------------------------------------------------
// 1) GEMM (tf32 tensor cores, 3xTF32): g_h = feat @ W
//    Block 128x64, 8 warps (4m x 2n), warp tile 32x32, KC=32.
//    A raw in smem (split at fragment load); B pre-split float2 in smem.
// ---------------------------------------------------------------------------
__global__ __launch_bounds__(256) void gemm_tf32_kernel(
    const float* __restrict__ feat)
{
    __shared__ float  As[128][36];   // raw A [m][k], padded
    __shared__ float2 Bs2[32][66];   // pre-split B [k][n], padded

    const int tid  = threadIdx.x;
    const int wid  = tid >> 5;
    const int lane = tid & 31;
    const int wm   = wid >> 1;      // 0..3
    const int wn   = wid & 1;       // 0..1
    const int gid  = lane >> 2;     // 0..7
    const int tig  = lane & 3;      // 0..3
    const int m0   = blockIdx.x * 128;

    float acc[2][4][4] = {};

    for (int k0 = 0; k0 < IN_F; k0 += 32) {
        // load A tile: 128 x 32 floats (1024 float4, 4 per thread)
        #pragma unroll
        for (int q = 0; q < 4; q++) {
            const int i = tid + q * 256;
            const int r  = i >> 3;
            const int c4 = (i & 7) * 4;
            float4 v = make_float4(0.f, 0.f, 0.f, 0.f);
            if (m0 + r < N_NODES)
                v = *reinterpret_cast<const float4*>(feat + (size_t)(m0 + r) * IN_F + k0 + c4);
            *reinterpret_cast<float4*>(&As[r][c4]) = v;
        }
        // load pre-split B tile: 32 x 64 float2 = 4096 floats = 1024 float4
        // (4 float4 per thread). g_Wsp is row-major [k][n] float2.
        #pragma unroll
        for (int q = 0; q < 4; q++) {
            const int j  = tid + q * 256;      // float4 index 0..1023
            const int p  = j * 2;              // float2 index 0..2046 (even)
            const int kk = p >> 6;             // k row 0..31
            const int nn = p & 63;             // n col (even)
            float4 v = *reinterpret_cast<const float4*>(
                reinterpret_cast<const float*>(g_Wsp) + (size_t)k0 * OUT_F * 2 + (size_t)j * 4);
            *reinterpret_cast<float4*>(&Bs2[kk][nn]) = v;
        }
        __syncthreads();

        #pragma unroll
        for (int kf = 0; kf < 4; kf++) {
            // A fragments (+ split at use)
            float2 fa[2][4];
            #pragma unroll
            for (int mf = 0; mf < 2; mf++) {
                const int r = wm * 32 + mf * 16 + gid;
                const int c = kf * 8 + tig;
                fa[mf][0] = split_tf32(As[r][c]);
                fa[mf][1] = split_tf32(As[r + 8][c]);
                fa[mf][2] = split_tf32(As[r][c + 4]);
                fa[mf][3] = split_tf32(As[r + 8][c + 4]);
            }
            // B fragments: pre-split LDS.64
            float2 fb[4][2];
            #pragma unroll
            for (int nf = 0; nf < 4; nf++) {
                const int c = wn * 32 + nf * 8 + gid;
                const int r = kf * 8 + tig;
                fb[nf][0] = Bs2[r][c];
                fb[nf][1] = Bs2[r + 4][c];
            }
            #pragma unroll
            for (int mf = 0; mf < 2; mf++)
                #pragma unroll
                for (int nf = 0; nf < 4; nf++) {
                    float* d = acc[mf][nf];
                    mma8(d[0], d[1], d[2], d[3],
                         fa[mf][0].x, fa[mf][1].x, fa[mf][2].x, fa[mf][3].x,
                         fb[nf][0].x, fb[nf][1].x);                      // big·big
                    mma8(d[0], d[1], d[2], d[3],
                         fa[mf][0].x, fa[mf][1].x, fa[mf][2].x, fa[mf][3].x,
                         fb[nf][0].y, fb[nf][1].y);                      // big·small
                    mma8(d[0], d[1], d[2], d[3],
                         fa[mf][0].y, fa[mf][1].y, fa[mf][2].y, fa[mf][3].y,
                         fb[nf][0].x, fb[nf][1].x);                      // small·big
                }
        }
        __syncthreads();
    }

    // epilogue
    #pragma unroll
    for (int mf = 0; mf < 2; mf++) {
        #pragma unroll
        for (int nf = 0; nf < 4; nf++) {
            const int c  = wn * 32 + nf * 8 + tig * 2;
            const int r0 = m0 + wm * 32 + mf * 16 + gid;
            if (r0 < N_NODES)
                *reinterpret_cast<float2*>(g_h + (size_t)r0 * OUT_F + c) =
                    make_float2(acc[mf][nf][0], acc[mf][nf][1]);
            if (r0 + 8 < N_NODES)
                *reinterpret_cast<float2*>(g_h + (size_t)(r0 + 8) * OUT_F + c) =
                    make_float2(acc[mf][nf][2], acc[mf][nf][3]);
        }
    }
}

// ---------------------------------------------------------------------------
// 2) Edge scatter: out[dst] += h[src] * w via red.global.add.v4.f32
// ---------------------------------------------------------------------------
__global__ __launch_bounds__(256) void edge_kernel(
    const int* __restrict__ src, const int* __restrict__ dst,
    const float* __restrict__ ew, float* __restrict__ out)
{
    const long long t = (long long)blockIdx.x * blockDim.x + threadIdx.x;
    const int e = (int)(t >> 4);
    const int l = (int)(t & 15);
    if (e >= N_EDGES) return;

    const int s = __ldg(src + e);
    const int d = __ldg(dst + e);
    const float w = __ldg(ew + e);

    float4 v = *reinterpret_cast<const float4*>(g_h + (size_t)s * OUT_F + l * 4);
    v.x *= w; v.y *= w; v.z *= w; v.w *= w;

    float* p = out + (size_t)d * OUT_F + l * 4;
    asm volatile("red.global.add.v4.f32 [%0], {%1,%2,%3,%4};"
                 :: "l"(p), "f"(v.x), "f"(v.y), "f"(v.z), "f"(v.w)
                 : "memory");

    if (l == 0) atomicAdd(&g_deg[d], 1.0f);
}

// ---------------------------------------------------------------------------
// 3) finalize (vectorized): out = relu( msum * (deg>0 ? 1/deg : 0) + bias )
// ---------------------------------------------------------------------------
__global__ void finalize_kernel(float4* __restrict__ out4, const float* __restrict__ bias) {
    const int i = blockIdx.x * blockDim.x + threadIdx.x;
    if (i >= N_NODES * OUT_F / 4) return;
    const int node = i >> 4;
    const int c4   = (i & 15) * 4;
    const float d  = g_deg[node];
    const float rinv = (d > 0.0f) ? (1.0f / d) : 0.0f;
    float4 v = out4[i];
    v.x = fmaxf(fmaf(v.x, rinv, __ldg(bias + c4 + 0)), 0.0f);
    v.y = fmaxf(fmaf(v.y, rinv, __ldg(bias + c4 + 1)), 0.0f);
    v.z = fmaxf(fmaf(v.z, rinv, __ldg(bias + c4 + 2)), 0.0f);
    v.w = fmaxf(fmaf(v.w, rinv, __ldg(bias + c4 + 3)), 0.0f);
    out4[i] = v;
}

// ---------------------------------------------------------------------------
extern "C" void kernel_launch(void* const* d_in, const int* in_sizes, int n_in,
                              void* d_out, int out_size)
{
    const float* feat     = (const float*)d_in[0];
    const float* edge_w   = (const float*)d_in[1];
    const float* weight   = (const float*)d_in[2];
    const float* bias     = (const float*)d_in[3];
    const int*   edge_src = (const int*)d_in[4];
    const int*   edge_dst = (const int*)d_in[5];
    float* out = (float*)d_out;

    zero_kernel<<<(N_NODES * OUT_F / 4 + 255) / 256, 256>>>((float4*)out);
    wsplit_kernel<<<(IN_F * OUT_F + 255) / 256, 256>>>(weight);
    gemm_tf32_kernel<<<(N_NODES + 127) / 128, 256>>>(feat);
    edge_kernel<<<(int)(((long long)N_EDGES * 16 + 255) / 256), 256>>>(edge_src, edge_dst, edge_w, out);
    finalize_kernel<<<(N_NODES * OUT_F / 4 + 255) / 256, 256>>>((float4*)out, bias);
}

// round 9
// speedup vs baseline: 1.3704x; 1.2911x over previous
#include <cuda_runtime.h>
#include <cuda_bf16.h>
#include <cstdint>

#define N_NODES 100000
#define N_EDGES 1600000
#define IN_F    512
#define OUT_F   64

// ---- scratch (__device__ globals) ------------------------------------------
__device__ float    g_h[(size_t)N_NODES * OUT_F];   // projected features
__device__ float    g_deg[N_NODES];                 // in-degree per dst node
// W pre-split, packed bf16 pairs along k: [kpair][n] -> uint = (bf16(k+1)<<16)|bf16(k)
__device__ unsigned g_Bhi[(IN_F / 2) * OUT_F];
__device__ unsigned g_Blo[(IN_F / 2) * OUT_F];

// ---- bf16 split helpers ------------------------------------------------------
// x = hi + lo (both bf16), lo = bf16(x - float(hi))
__device__ __forceinline__ void split_bf16(float x, __nv_bfloat16& hi, __nv_bfloat16& lo) {
    hi = __float2bfloat16_rn(x);
    lo = __float2bfloat16_rn(x - __bfloat162float(hi));
}
__device__ __forceinline__ unsigned pack_bf16(__nv_bfloat16 a, __nv_bfloat16 b) {
    unsigned short ua = *reinterpret_cast<unsigned short*>(&a);
    unsigned short ub = *reinterpret_cast<unsigned short*>(&b);
    return (unsigned)ua | ((unsigned)ub << 16);
}

__device__ __forceinline__ void mma16(float& d0, float& d1, float& d2, float& d3,
                                      unsigned a0, unsigned a1, unsigned a2, unsigned a3,
                                      unsigned b0, unsigned b1) {
    asm volatile("mma.sync.aligned.m16n8k16.row.col.f32.bf16.bf16.f32 "
                 "{%0,%1,%2,%3},{%4,%5,%6,%7},{%8,%9},{%0,%1,%2,%3};"
                 : "+f"(d0), "+f"(d1), "+f"(d2), "+f"(d3)
                 : "r"(a0), "r"(a1), "r"(a2), "r"(a3), "r"(b0), "r"(b1));
}

// ---------------------------------------------------------------------------
// 0) zero output accumulator + degree counters
// ---------------------------------------------------------------------------
__global__ void zero_kernel(float4* __restrict__ out4) {
    int i = blockIdx.x * blockDim.x + threadIdx.x;
    if (i < N_NODES * OUT_F / 4) out4[i] = make_float4(0.f, 0.f, 0.f, 0.f);
    if (i < N_NODES) g_deg[i] = 0.0f;
}

// ---------------------------------------------------------------------------
// 0b) split W into bf16 (hi, lo), packed pairs along k: [kpair][n]
//     W is [k][n] row-major (n contiguous).
// ---------------------------------------------------------------------------
__global__ void wsplit_kernel(const float* __restrict__ W) {
    int i = blockIdx.x * blockDim.x + threadIdx.x;          // over (IN_F/2)*OUT_F
    if (i >= (IN_F / 2) * OUT_F) return;
    const int kp = i >> 6;          // kpair
    const int n  = i & 63;
    const float x0 = W[(size_t)(2 * kp)     * OUT_F + n];
    const float x1 = W[(size_t)(2 * kp + 1) * OUT_F + n];
    __nv_bfloat16 h0, l0, h1, l1;
    split_bf16(x0, h0, l0);
    split_bf16(x1, h1, l1);
    g_Bhi[i] = pack_bf16(h0, h1);
    g_Blo[i] = pack_bf16(l0, l1);
}

// ---------------------------------------------------------------------------
// 1) GEMM (bf16 tensor cores, 3xBF16 compensated): g_h = feat @ W
//    Block 128x64, 8 warps (4m x 2n), warp tile 32x32, KC=32 (2 x k16).
//    A split to bf16 hi/lo at tile load; B pre-split global -> smem copy.
// ---------------------------------------------------------------------------
__global__ __launch_bounds__(256) void gemm_bf16_kernel(
    const float* __restrict__ feat)
{
    // packed bf16 pairs along k
    __shared__ unsigned As_hi[128][20];   // [m][kpair], 16 pairs + pad
    __shared__ unsigned As_lo[128][20];
    __shared__ unsigned Bs_hi[16][72];    // [kpair][n], pad 72 for bank-split
    __shared__ unsigned Bs_lo[16][72];

    const int tid  = threadIdx.x;
    const int wid  = tid >> 5;
    const int lane = tid & 31;
    const int wm   = wid >> 1;      // 0..3
    const int wn   = wid & 1;       // 0..1
    const int gid  = lane >> 2;     // 0..7
    const int tig  = lane & 3;      // 0..3
    const int m0   = blockIdx.x * 128;

    float acc[2][4][4] = {};

    for (int k0 = 0; k0 < IN_F; k0 += 32) {
        // --- A tile: 128 rows x 32 floats = 1024 float4 (4 per thread) ---
        #pragma unroll
        for (int q = 0; q < 4; q++) {
            const int i  = tid + q * 256;
            const int r  = i >> 3;
            const int f4 = i & 7;                 // float4 index along k
            float4 v = make_float4(0.f, 0.f, 0.f, 0.f);
            if (m0 + r < N_NODES)
                v = *reinterpret_cast<const float4*>(feat + (size_t)(m0 + r) * IN_F + k0 + f4 * 4);
            __nv_bfloat16 hx, lx, hy, ly, hz, lz, hw, lw;
            split_bf16(v.x, hx, lx); split_bf16(v.y, hy, ly);
            split_bf16(v.z, hz, lz); split_bf16(v.w, hw, lw);
            As_hi[r][f4 * 2]     = pack_bf16(hx, hy);
            As_hi[r][f4 * 2 + 1] = pack_bf16(hz, hw);
            As_lo[r][f4 * 2]     = pack_bf16(lx, ly);
            As_lo[r][f4 * 2 + 1] = pack_bf16(lz, lw);
        }
        // --- B tile: 16 kpairs x 64 n = 1024 uints = 256 uint4 (1 per thread) ---
        {
            const int j  = tid;                   // 0..255
            const int kp = j >> 4;                // 0..15
            const int n4 = (j & 15) * 4;
            const size_t gidx = (size_t)(k0 / 2 + kp) * OUT_F + n4;
            uint4 vh = *reinterpret_cast<const uint4*>(g_Bhi + gidx);
            uint4 vl = *reinterpret_cast<const uint4*>(g_Blo + gidx);
            *reinterpret_cast<uint4*>(&Bs_hi[kp][n4]) = vh;
            *reinterpret_cast<uint4*>(&Bs_lo[kp][n4]) = vl;
        }
        __syncthreads();

        #pragma unroll
        for (int kf = 0; kf < 2; kf++) {          // two k16 steps per K32 tile
            const int pb = kf * 8;                // kpair base
            // A fragments
            unsigned ah[2][4], al[2][4];
            #pragma unroll
            for (int mf = 0; mf < 2; mf++) {
                const int r = wm * 32 + mf * 16 + gid;
                ah[mf][0] = As_hi[r][pb + tig];
                ah[mf][1] = As_hi[r + 8][pb + tig];
                ah[mf][2] = As_hi[r][pb + tig + 4];
                ah[mf][3] = As_hi[r + 8][pb + tig + 4];
                al[mf][0] = As_lo[r][pb + tig];
                al[mf][1] = As_lo[r + 8][pb + tig];
                al[mf][2] = As_lo[r][pb + tig + 4];
                al[mf][3] = As_lo[r + 8][pb + tig + 4];
            }
            // B fragments
            unsigned bh[4][2], bl[4][2];
            #pragma unroll
            for (int nf = 0; nf < 4; nf++) {
                const int c = wn * 32 + nf * 8 + gid;
                bh[nf][0] = Bs_hi[pb + tig][c];
                bh[nf][1] = Bs_hi[pb + tig + 4][c];
                bl[nf][0] = Bs_lo[pb + tig][c];
                bl[nf][1] = Bs_lo[pb + tig + 4][c];
            }
            #pragma unroll
            for (int mf = 0; mf < 2; mf++)
                #pragma unroll
                for (int nf = 0; nf < 4; nf++) {
                    float* d = acc[mf][nf];
                    mma16(d[0], d[1], d[2], d[3],
                          ah[mf][0], ah[mf][1], ah[mf][2], ah[mf][3],
                          bh[nf][0], bh[nf][1]);                 // hi·hi
                    mma16(d[0], d[1], d[2], d[3],
                          ah[mf][0], ah[mf][1], ah[mf][2], ah[mf][3],
                          bl[nf][0], bl[nf][1]);                 // hi·lo
                    mma16(d[0], d[1], d[2], d[3],
                          al[mf][0], al[mf][1], al[mf][2], al[mf][3],
                          bh[nf][0], bh[nf][1]);                 // lo·hi
                }
        }
        __syncthreads();
    }

    // epilogue: d0,d1 -> (row, 2tig..2tig+1); d2,d3 -> (row+8, ...)
    #pragma unroll
    for (int mf = 0; mf < 2; mf++) {
        #pragma unroll
        for (int nf = 0; nf < 4; nf++) {
            const int c  = wn * 32 + nf * 8 + tig * 2;
            const int r0 = m0 + wm * 32 + mf * 16 + gid;
            if (r0 < N_NODES)
                *reinterpret_cast<float2*>(g_h + (size_t)r0 * OUT_F + c) =
                    make_float2(acc[mf][nf][0], acc[mf][nf][1]);
            if (r0 + 8 < N_NODES)
                *reinterpret_cast<float2*>(g_h + (size_t)(r0 + 8) * OUT_F + c) =
                    make_float2(acc[mf][nf][2], acc[mf][nf][3]);
        }
    }
}

// ---------------------------------------------------------------------------
// 2) Edge scatter: out[dst] += h[src] * w via red.global.add.v4.f32
// ---------------------------------------------------------------------------
__global__ __launch_bounds__(256) void edge_kernel(
    const int* __restrict__ src, const int* __restrict__ dst,
    const float* __restrict__ ew, float* __restrict__ out)
{
    const long long t = (long long)blockIdx.x * blockDim.x + threadIdx.x;
    const int e = (int)(t >> 4);
    const int l = (int)(t & 15);
    if (e >= N_EDGES) return;

    const int s = __ldg(src + e);
    const int d = __ldg(dst + e);
    const float w = __ldg(ew + e);

    float4 v = *reinterpret_cast<const float4*>(g_h + (size_t)s * OUT_F + l * 4);
    v.x *= w; v.y *= w; v.z *= w; v.w *= w;

    float* p = out + (size_t)d * OUT_F + l * 4;
    asm volatile("red.global.add.v4.f32 [%0], {%1,%2,%3,%4};"
                 :: "l"(p), "f"(v.x), "f"(v.y), "f"(v.z), "f"(v.w)
                 : "memory");

    if (l == 0) atomicAdd(&g_deg[d], 1.0f);
}

// ---------------------------------------------------------------------------
// 3) finalize (vectorized): out = relu( msum * (deg>0 ? 1/deg : 0) + bias )
// ---------------------------------------------------------------------------
__global__ void finalize_kernel(float4* __restrict__ out4, const float* __restrict__ bias) {
    const int i = blockIdx.x * blockDim.x + threadIdx.x;
    if (i >= N_NODES * OUT_F / 4) return;
    const int node = i >> 4;
    const int c4   = (i & 15) * 4;
    const float d  = g_deg[node];
    const float rinv = (d > 0.0f) ? (1.0f / d) : 0.0f;
    float4 v = out4[i];
    v.x = fmaxf(fmaf(v.x, rinv, __ldg(bias + c4 + 0)), 0.0f);
    v.y = fmaxf(fmaf(v.y, rinv, __ldg(bias + c4 + 1)), 0.0f);
    v.z = fmaxf(fmaf(v.z, rinv, __ldg(bias + c4 + 2)), 0.0f);
    v.w = fmaxf(fmaf(v.w, rinv, __ldg(bias + c4 + 3)), 0.0f);
    out4[i] = v;
}

// ---------------------------------------------------------------------------
extern "C" void kernel_launch(void* const* d_in, const int* in_sizes, int n_in,
                              void* d_out, int out_size)
{
    const float* feat     = (const float*)d_in[0];
    const float* edge_w   = (const float*)d_in[1];
    const float* weight   = (const float*)d_in[2];
    const float* bias     = (const float*)d_in[3];
    const int*   edge_src = (const int*)d_in[4];
    const int*   edge_dst = (const int*)d_in[5];
    float* out = (float*)d_out;

    zero_kernel<<<(N_NODES * OUT_F / 4 + 255) / 256, 256>>>((float4*)out);
    wsplit_kernel<<<((IN_F / 2) * OUT_F + 255) / 256, 256>>>(weight);
    gemm_bf16_kernel<<<(N_NODES + 127) / 128, 256>>>(feat);
    edge_kernel<<<(int)(((long long)N_EDGES * 16 + 255) / 256), 256>>>(edge_src, edge_dst, edge_w, out);
    finalize_kernel<<<(N_NODES * OUT_F / 4 + 255) / 256, 256>>>((float4*)out, bias);
}

// round 10
// speedup vs baseline: 1.4494x; 1.0577x over previous
#include <cuda_runtime.h>
#include <cuda_bf16.h>
#include <cstdint>

#define N_NODES 100000
#define N_EDGES 1600000
#define IN_F    512
#define OUT_F   64
#define HALF_E  (N_EDGES / 2)

// ---- scratch (__device__ globals) ------------------------------------------
__device__ float    g_h[(size_t)N_NODES * OUT_F];   // projected features
__device__ float    g_deg[N_NODES];                 // in-degree per dst node
// W pre-split, packed bf16 pairs along k: [kpair][n] -> uint = (bf16(k+1)<<16)|bf16(k)
__device__ unsigned g_Bhi[(IN_F / 2) * OUT_F];
__device__ unsigned g_Blo[(IN_F / 2) * OUT_F];

// ---- bf16 split helpers ------------------------------------------------------
__device__ __forceinline__ void split_bf16(float x, __nv_bfloat16& hi, __nv_bfloat16& lo) {
    hi = __float2bfloat16_rn(x);
    lo = __float2bfloat16_rn(x - __bfloat162float(hi));
}
__device__ __forceinline__ unsigned pack_bf16(__nv_bfloat16 a, __nv_bfloat16 b) {
    unsigned short ua = *reinterpret_cast<unsigned short*>(&a);
    unsigned short ub = *reinterpret_cast<unsigned short*>(&b);
    return (unsigned)ua | ((unsigned)ub << 16);
}

__device__ __forceinline__ void mma16(float& d0, float& d1, float& d2, float& d3,
                                      unsigned a0, unsigned a1, unsigned a2, unsigned a3,
                                      unsigned b0, unsigned b1) {
    asm volatile("mma.sync.aligned.m16n8k16.row.col.f32.bf16.bf16.f32 "
                 "{%0,%1,%2,%3},{%4,%5,%6,%7},{%8,%9},{%0,%1,%2,%3};"
                 : "+f"(d0), "+f"(d1), "+f"(d2), "+f"(d3)
                 : "r"(a0), "r"(a1), "r"(a2), "r"(a3), "r"(b0), "r"(b1));
}

// ---------------------------------------------------------------------------
// 0) zero output accumulator + degree counters
// ---------------------------------------------------------------------------
__global__ void zero_kernel(float4* __restrict__ out4) {
    int i = blockIdx.x * blockDim.x + threadIdx.x;
    if (i < N_NODES * OUT_F / 4) out4[i] = make_float4(0.f, 0.f, 0.f, 0.f);
    if (i < N_NODES) g_deg[i] = 0.0f;
}

// ---------------------------------------------------------------------------
// 0b) split W into bf16 (hi, lo), packed pairs along k: [kpair][n]
// ---------------------------------------------------------------------------
__global__ void wsplit_kernel(const float* __restrict__ W) {
    int i = blockIdx.x * blockDim.x + threadIdx.x;
    if (i >= (IN_F / 2) * OUT_F) return;
    const int kp = i >> 6;
    const int n  = i & 63;
    const float x0 = W[(size_t)(2 * kp)     * OUT_F + n];
    const float x1 = W[(size_t)(2 * kp + 1) * OUT_F + n];
    __nv_bfloat16 h0, l0, h1, l1;
    split_bf16(x0, h0, l0);
    split_bf16(x1, h1, l1);
    g_Bhi[i] = pack_bf16(h0, h1);
    g_Blo[i] = pack_bf16(l0, l1);
}

// ---------------------------------------------------------------------------
// 1) GEMM (bf16 tensor cores, 3xBF16 compensated): g_h = feat @ W
//    (unchanged from R9: 225 µs kernel, GEMM ~85 µs)
// ---------------------------------------------------------------------------
__global__ __launch_bounds__(256) void gemm_bf16_kernel(
    const float* __restrict__ feat)
{
    __shared__ unsigned As_hi[128][20];
    __shared__ unsigned As_lo[128][20];
    __shared__ unsigned Bs_hi[16][72];
    __shared__ unsigned Bs_lo[16][72];

    const int tid  = threadIdx.x;
    const int wid  = tid >> 5;
    const int lane = tid & 31;
    const int wm   = wid >> 1;
    const int wn   = wid & 1;
    const int gid  = lane >> 2;
    const int tig  = lane & 3;
    const int m0   = blockIdx.x * 128;

    float acc[2][4][4] = {};

    for (int k0 = 0; k0 < IN_F; k0 += 32) {
        #pragma unroll
        for (int q = 0; q < 4; q++) {
            const int i  = tid + q * 256;
            const int r  = i >> 3;
            const int f4 = i & 7;
            float4 v = make_float4(0.f, 0.f, 0.f, 0.f);
            if (m0 + r < N_NODES)
                v = *reinterpret_cast<const float4*>(feat + (size_t)(m0 + r) * IN_F + k0 + f4 * 4);
            __nv_bfloat16 hx, lx, hy, ly, hz, lz, hw, lw;
            split_bf16(v.x, hx, lx); split_bf16(v.y, hy, ly);
            split_bf16(v.z, hz, lz); split_bf16(v.w, hw, lw);
            As_hi[r][f4 * 2]     = pack_bf16(hx, hy);
            As_hi[r][f4 * 2 + 1] = pack_bf16(hz, hw);
            As_lo[r][f4 * 2]     = pack_bf16(lx, ly);
            As_lo[r][f4 * 2 + 1] = pack_bf16(lz, lw);
        }
        {
            const int j  = tid;
            const int kp = j >> 4;
            const int n4 = (j & 15) * 4;
            const size_t gidx = (size_t)(k0 / 2 + kp) * OUT_F + n4;
            uint4 vh = *reinterpret_cast<const uint4*>(g_Bhi + gidx);
            uint4 vl = *reinterpret_cast<const uint4*>(g_Blo + gidx);
            *reinterpret_cast<uint4*>(&Bs_hi[kp][n4]) = vh;
            *reinterpret_cast<uint4*>(&Bs_lo[kp][n4]) = vl;
        }
        __syncthreads();

        #pragma unroll
        for (int kf = 0; kf < 2; kf++) {
            const int pb = kf * 8;
            unsigned ah[2][4], al[2][4];
            #pragma unroll
            for (int mf = 0; mf < 2; mf++) {
                const int r = wm * 32 + mf * 16 + gid;
                ah[mf][0] = As_hi[r][pb + tig];
                ah[mf][1] = As_hi[r + 8][pb + tig];
                ah[mf][2] = As_hi[r][pb + tig + 4];
                ah[mf][3] = As_hi[r + 8][pb + tig + 4];
                al[mf][0] = As_lo[r][pb + tig];
                al[mf][1] = As_lo[r + 8][pb + tig];
                al[mf][2] = As_lo[r][pb + tig + 4];
                al[mf][3] = As_lo[r + 8][pb + tig + 4];
            }
            unsigned bh[4][2], bl[4][2];
            #pragma unroll
            for (int nf = 0; nf < 4; nf++) {
                const int c = wn * 32 + nf * 8 + gid;
                bh[nf][0] = Bs_hi[pb + tig][c];
                bh[nf][1] = Bs_hi[pb + tig + 4][c];
                bl[nf][0] = Bs_lo[pb + tig][c];
                bl[nf][1] = Bs_lo[pb + tig + 4][c];
            }
            #pragma unroll
            for (int mf = 0; mf < 2; mf++)
                #pragma unroll
                for (int nf = 0; nf < 4; nf++) {
                    float* d = acc[mf][nf];
                    mma16(d[0], d[1], d[2], d[3],
                          ah[mf][0], ah[mf][1], ah[mf][2], ah[mf][3],
                          bh[nf][0], bh[nf][1]);
                    mma16(d[0], d[1], d[2], d[3],
                          ah[mf][0], ah[mf][1], ah[mf][2], ah[mf][3],
                          bl[nf][0], bl[nf][1]);
                    mma16(d[0], d[1], d[2], d[3],
                          al[mf][0], al[mf][1], al[mf][2], al[mf][3],
                          bh[nf][0], bh[nf][1]);
                }
        }
        __syncthreads();
    }

    #pragma unroll
    for (int mf = 0; mf < 2; mf++) {
        #pragma unroll
        for (int nf = 0; nf < 4; nf++) {
            const int c  = wn * 32 + nf * 8 + tig * 2;
            const int r0 = m0 + wm * 32 + mf * 16 + gid;
            if (r0 < N_NODES)
                *reinterpret_cast<float2*>(g_h + (size_t)r0 * OUT_F + c) =
                    make_float2(acc[mf][nf][0], acc[mf][nf][1]);
            if (r0 + 8 < N_NODES)
                *reinterpret_cast<float2*>(g_h + (size_t)(r0 + 8) * OUT_F + c) =
                    make_float2(acc[mf][nf][2], acc[mf][nf][3]);
        }
    }
}

// ---------------------------------------------------------------------------
// 2) Edge scatter, MLP=2: each thread handles TWO independent edges.
//    16 threads per edge, float4 each. Gathers issued back-to-back before REDs.
// ---------------------------------------------------------------------------
__global__ __launch_bounds__(256) void edge_kernel(
    const int* __restrict__ src, const int* __restrict__ dst,
    const float* __restrict__ ew, float* __restrict__ out)
{
    const long long t = (long long)blockIdx.x * blockDim.x + threadIdx.x;
    const int e0 = (int)(t >> 4);
    const int l  = (int)(t & 15);
    if (e0 >= HALF_E) return;
    const int e1 = e0 + HALF_E;

    const int   s0 = __ldg(src + e0);
    const int   d0 = __ldg(dst + e0);
    const float w0 = __ldg(ew  + e0);
    const int   s1 = __ldg(src + e1);
    const int   d1 = __ldg(dst + e1);
    const float w1 = __ldg(ew  + e1);

    float4 v0 = *reinterpret_cast<const float4*>(g_h + (size_t)s0 * OUT_F + l * 4);
    float4 v1 = *reinterpret_cast<const float4*>(g_h + (size_t)s1 * OUT_F + l * 4);

    v0.x *= w0; v0.y *= w0; v0.z *= w0; v0.w *= w0;
    v1.x *= w1; v1.y *= w1; v1.z *= w1; v1.w *= w1;

    float* p0 = out + (size_t)d0 * OUT_F + l * 4;
    float* p1 = out + (size_t)d1 * OUT_F + l * 4;
    asm volatile("red.global.add.v4.f32 [%0], {%1,%2,%3,%4};"
                 :: "l"(p0), "f"(v0.x), "f"(v0.y), "f"(v0.z), "f"(v0.w) : "memory");
    asm volatile("red.global.add.v4.f32 [%0], {%1,%2,%3,%4};"
                 :: "l"(p1), "f"(v1.x), "f"(v1.y), "f"(v1.z), "f"(v1.w) : "memory");

    if (l == 0) {
        atomicAdd(&g_deg[d0], 1.0f);
        atomicAdd(&g_deg[d1], 1.0f);
    }
}

// ---------------------------------------------------------------------------
// 3) finalize (vectorized): out = relu( msum * (deg>0 ? 1/deg : 0) + bias )
// ---------------------------------------------------------------------------
__global__ void finalize_kernel(float4* __restrict__ out4, const float* __restrict__ bias) {
    const int i = blockIdx.x * blockDim.x + threadIdx.x;
    if (i >= N_NODES * OUT_F / 4) return;
    const int node = i >> 4;
    const int c4   = (i & 15) * 4;
    const float d  = g_deg[node];
    const float rinv = (d > 0.0f) ? (1.0f / d) : 0.0f;
    float4 v = out4[i];
    v.x = fmaxf(fmaf(v.x, rinv, __ldg(bias + c4 + 0)), 0.0f);
    v.y = fmaxf(fmaf(v.y, rinv, __ldg(bias + c4 + 1)), 0.0f);
    v.z = fmaxf(fmaf(v.z, rinv, __ldg(bias + c4 + 2)), 0.0f);
    v.w = fmaxf(fmaf(v.w, rinv, __ldg(bias + c4 + 3)), 0.0f);
    out4[i] = v;
}

// ---------------------------------------------------------------------------
extern "C" void kernel_launch(void* const* d_in, const int* in_sizes, int n_in,
                              void* d_out, int out_size)
{
    const float* feat     = (const float*)d_in[0];
    const float* edge_w   = (const float*)d_in[1];
    const float* weight   = (const float*)d_in[2];
    const float* bias     = (const float*)d_in[3];
    const int*   edge_src = (const int*)d_in[4];
    const int*   edge_dst = (const int*)d_in[5];
    float* out = (float*)d_out;

    zero_kernel<<<(N_NODES * OUT_F / 4 + 255) / 256, 256>>>((float4*)out);
    wsplit_kernel<<<((IN_F / 2) * OUT_F + 255) / 256, 256>>>(weight);
    gemm_bf16_kernel<<<(N_NODES + 127) / 128, 256>>>(feat);
    edge_kernel<<<(int)(((long long)HALF_E * 16 + 255) / 256), 256>>>(edge_src, edge_dst, edge_w, out);
    finalize_kernel<<<(N_NODES * OUT_F / 4 + 255) / 256, 256>>>((float4*)out, bias);
}

// round 11
// speedup vs baseline: 1.7130x; 1.1819x over previous
#include <cuda_runtime.h>
#include <cuda_bf16.h>
#include <cstdint>

#define N_NODES 100000
#define N_EDGES 1600000
#define IN_F    512
#define OUT_F   64
#define QRT_E   (N_EDGES / 4)

// ---- scratch (__device__ globals) ------------------------------------------
__device__ float    g_h[(size_t)N_NODES * OUT_F];   // projected features
__device__ float    g_deg[N_NODES];                 // in-degree per dst node
// W pre-split, packed bf16 pairs along k: [kpair][n]
__device__ unsigned g_Bhi[(IN_F / 2) * OUT_F];
__device__ unsigned g_Blo[(IN_F / 2) * OUT_F];

// ---- bf16 split helpers ------------------------------------------------------
__device__ __forceinline__ void split_bf16(float x, __nv_bfloat16& hi, __nv_bfloat16& lo) {
    hi = __float2bfloat16_rn(x);
    lo = __float2bfloat16_rn(x - __bfloat162float(hi));
}
__device__ __forceinline__ unsigned pack_bf16(__nv_bfloat16 a, __nv_bfloat16 b) {
    unsigned short ua = *reinterpret_cast<unsigned short*>(&a);
    unsigned short ub = *reinterpret_cast<unsigned short*>(&b);
    return (unsigned)ua | ((unsigned)ub << 16);
}

__device__ __forceinline__ void mma16(float& d0, float& d1, float& d2, float& d3,
                                      unsigned a0, unsigned a1, unsigned a2, unsigned a3,
                                      unsigned b0, unsigned b1) {
    asm volatile("mma.sync.aligned.m16n8k16.row.col.f32.bf16.bf16.f32 "
                 "{%0,%1,%2,%3},{%4,%5,%6,%7},{%8,%9},{%0,%1,%2,%3};"
                 : "+f"(d0), "+f"(d1), "+f"(d2), "+f"(d3)
                 : "r"(a0), "r"(a1), "r"(a2), "r"(a3), "r"(b0), "r"(b1));
}

// ---------------------------------------------------------------------------
// 0) fused init: zero out + deg, pre-split W
// ---------------------------------------------------------------------------
__global__ void init_kernel(float4* __restrict__ out4, const float* __restrict__ W) {
    const int i = blockIdx.x * blockDim.x + threadIdx.x;
    if (i < N_NODES * OUT_F / 4) out4[i] = make_float4(0.f, 0.f, 0.f, 0.f);
    if (i < N_NODES) g_deg[i] = 0.0f;
    if (i < (IN_F / 2) * OUT_F) {
        const int kp = i >> 6;
        const int n  = i & 63;
        const float x0 = W[(size_t)(2 * kp)     * OUT_F + n];
        const float x1 = W[(size_t)(2 * kp + 1) * OUT_F + n];
        __nv_bfloat16 h0, l0, h1, l1;
        split_bf16(x0, h0, l0);
        split_bf16(x1, h1, l1);
        g_Bhi[i] = pack_bf16(h0, h1);
        g_Blo[i] = pack_bf16(l0, l1);
    }
}

// ---------------------------------------------------------------------------
// 1) GEMM (bf16 tensor cores, 3xBF16 compensated) with A register prefetch.
//    Block 128x64, 8 warps (4m x 2n), warp tile 32x32, KC=32 (2 x k16).
// ---------------------------------------------------------------------------
__global__ __launch_bounds__(256) void gemm_bf16_kernel(
    const float* __restrict__ feat)
{
    __shared__ unsigned As_hi[128][20];
    __shared__ unsigned As_lo[128][20];
    __shared__ unsigned Bs_hi[16][72];
    __shared__ unsigned Bs_lo[16][72];

    const int tid  = threadIdx.x;
    const int wid  = tid >> 5;
    const int lane = tid & 31;
    const int wm   = wid >> 1;
    const int wn   = wid & 1;
    const int gid  = lane >> 2;
    const int tig  = lane & 3;
    const int m0   = blockIdx.x * 128;

    // A loader mapping (fixed per thread): 4 float4 chunks
    const int lr[4] = { (tid) >> 3, (tid + 256) >> 3, (tid + 512) >> 3, (tid + 768) >> 3 };
    const int lf    = tid & 7;   // float4 index along k (same for all 4 chunks)

    float acc[2][4][4] = {};
    float4 ra[4];

    // prologue: load A chunk for k0 = 0
    #pragma unroll
    for (int q = 0; q < 4; q++) {
        ra[q] = make_float4(0.f, 0.f, 0.f, 0.f);
        if (m0 + lr[q] < N_NODES)
            ra[q] = *reinterpret_cast<const float4*>(feat + (size_t)(m0 + lr[q]) * IN_F + lf * 4);
    }

    for (int k0 = 0; k0 < IN_F; k0 += 32) {
        // store prefetched A (split) to smem
        #pragma unroll
        for (int q = 0; q < 4; q++) {
            __nv_bfloat16 hx, lx, hy, ly, hz, lz, hw, lw;
            split_bf16(ra[q].x, hx, lx); split_bf16(ra[q].y, hy, ly);
            split_bf16(ra[q].z, hz, lz); split_bf16(ra[q].w, hw, lw);
            As_hi[lr[q]][lf * 2]     = pack_bf16(hx, hy);
            As_hi[lr[q]][lf * 2 + 1] = pack_bf16(hz, hw);
            As_lo[lr[q]][lf * 2]     = pack_bf16(lx, ly);
            As_lo[lr[q]][lf * 2 + 1] = pack_bf16(lz, lw);
        }
        // B tile: 16 kpairs x 64 n = 256 uint4 (1 per thread), hits L2 after tile 0
        {
            const int kp = tid >> 4;
            const int n4 = (tid & 15) * 4;
            const size_t gidx = (size_t)(k0 / 2 + kp) * OUT_F + n4;
            *reinterpret_cast<uint4*>(&Bs_hi[kp][n4]) = *reinterpret_cast<const uint4*>(g_Bhi + gidx);
            *reinterpret_cast<uint4*>(&Bs_lo[kp][n4]) = *reinterpret_cast<const uint4*>(g_Blo + gidx);
        }
        __syncthreads();

        // prefetch next A tile (LDG latency overlaps the MMA block below)
        const int kn = k0 + 32;
        if (kn < IN_F) {
            #pragma unroll
            for (int q = 0; q < 4; q++) {
                ra[q] = make_float4(0.f, 0.f, 0.f, 0.f);
                if (m0 + lr[q] < N_NODES)
                    ra[q] = *reinterpret_cast<const float4*>(feat + (size_t)(m0 + lr[q]) * IN_F + kn + lf * 4);
            }
        }

        #pragma unroll
        for (int kf = 0; kf < 2; kf++) {
            const int pb = kf * 8;
            unsigned ah[2][4], al[2][4];
            #pragma unroll
            for (int mf = 0; mf < 2; mf++) {
                const int r = wm * 32 + mf * 16 + gid;
                ah[mf][0] = As_hi[r][pb + tig];
                ah[mf][1] = As_hi[r + 8][pb + tig];
                ah[mf][2] = As_hi[r][pb + tig + 4];
                ah[mf][3] = As_hi[r + 8][pb + tig + 4];
                al[mf][0] = As_lo[r][pb + tig];
                al[mf][1] = As_lo[r + 8][pb + tig];
                al[mf][2] = As_lo[r][pb + tig + 4];
                al[mf][3] = As_lo[r + 8][pb + tig + 4];
            }
            unsigned bh[4][2], bl[4][2];
            #pragma unroll
            for (int nf = 0; nf < 4; nf++) {
                const int c = wn * 32 + nf * 8 + gid;
                bh[nf][0] = Bs_hi[pb + tig][c];
                bh[nf][1] = Bs_hi[pb + tig + 4][c];
                bl[nf][0] = Bs_lo[pb + tig][c];
                bl[nf][1] = Bs_lo[pb + tig + 4][c];
            }
            #pragma unroll
            for (int mf = 0; mf < 2; mf++)
                #pragma unroll
                for (int nf = 0; nf < 4; nf++) {
                    float* d = acc[mf][nf];
                    mma16(d[0], d[1], d[2], d[3],
                          ah[mf][0], ah[mf][1], ah[mf][2], ah[mf][3],
                          bh[nf][0], bh[nf][1]);
                    mma16(d[0], d[1], d[2], d[3],
                          ah[mf][0], ah[mf][1], ah[mf][2], ah[mf][3],
                          bl[nf][0], bl[nf][1]);
                    mma16(d[0], d[1], d[2], d[3],
                          al[mf][0], al[mf][1], al[mf][2], al[mf][3],
                          bh[nf][0], bh[nf][1]);
                }
        }
        __syncthreads();
    }

    #pragma unroll
    for (int mf = 0; mf < 2; mf++) {
        #pragma unroll
        for (int nf = 0; nf < 4; nf++) {
            const int c  = wn * 32 + nf * 8 + tig * 2;
            const int r0 = m0 + wm * 32 + mf * 16 + gid;
            if (r0 < N_NODES)
                *reinterpret_cast<float2*>(g_h + (size_t)r0 * OUT_F + c) =
                    make_float2(acc[mf][nf][0], acc[mf][nf][1]);
            if (r0 + 8 < N_NODES)
                *reinterpret_cast<float2*>(g_h + (size_t)(r0 + 8) * OUT_F + c) =
                    make_float2(acc[mf][nf][2], acc[mf][nf][3]);
        }
    }
}

// ---------------------------------------------------------------------------
// 2) Edge scatter, MLP=4: each thread handles FOUR independent edges.
// ---------------------------------------------------------------------------
__global__ __launch_bounds__(256) void edge_kernel(
    const int* __restrict__ src, const int* __restrict__ dst,
    const float* __restrict__ ew, float* __restrict__ out)
{
    const long long t = (long long)blockIdx.x * blockDim.x + threadIdx.x;
    const int e0 = (int)(t >> 4);
    const int l  = (int)(t & 15);
    if (e0 >= QRT_E) return;

    int   s[4], d[4];
    float w[4];
    #pragma unroll
    for (int q = 0; q < 4; q++) {
        const int e = e0 + q * QRT_E;
        s[q] = __ldg(src + e);
        d[q] = __ldg(dst + e);
        w[q] = __ldg(ew  + e);
    }

    float4 v[4];
    #pragma unroll
    for (int q = 0; q < 4; q++)
        v[q] = *reinterpret_cast<const float4*>(g_h + (size_t)s[q] * OUT_F + l * 4);

    #pragma unroll
    for (int q = 0; q < 4; q++) {
        v[q].x *= w[q]; v[q].y *= w[q]; v[q].z *= w[q]; v[q].w *= w[q];
        float* p = out + (size_t)d[q] * OUT_F + l * 4;
        asm volatile("red.global.add.v4.f32 [%0], {%1,%2,%3,%4};"
                     :: "l"(p), "f"(v[q].x), "f"(v[q].y), "f"(v[q].z), "f"(v[q].w)
                     : "memory");
    }

    if (l == 0) {
        #pragma unroll
        for (int q = 0; q < 4; q++) atomicAdd(&g_deg[d[q]], 1.0f);
    }
}

// ---------------------------------------------------------------------------
// 3) finalize (vectorized): out = relu( msum * (deg>0 ? 1/deg : 0) + bias )
// ---------------------------------------------------------------------------
__global__ void finalize_kernel(float4* __restrict__ out4, const float* __restrict__ bias) {
    const int i = blockIdx.x * blockDim.x + threadIdx.x;
    if (i >= N_NODES * OUT_F / 4) return;
    const int node = i >> 4;
    const int c4   = (i & 15) * 4;
    const float d  = g_deg[node];
    const float rinv = (d > 0.0f) ? (1.0f / d) : 0.0f;
    float4 v = out4[i];
    v.x = fmaxf(fmaf(v.x, rinv, __ldg(bias + c4 + 0)), 0.0f);
    v.y = fmaxf(fmaf(v.y, rinv, __ldg(bias + c4 + 1)), 0.0f);
    v.z = fmaxf(fmaf(v.z, rinv, __ldg(bias + c4 + 2)), 0.0f);
    v.w = fmaxf(fmaf(v.w, rinv, __ldg(bias + c4 + 3)), 0.0f);
    out4[i] = v;
}

// ---------------------------------------------------------------------------
extern "C" void kernel_launch(void* const* d_in, const int* in_sizes, int n_in,
                              void* d_out, int out_size)
{
    const float* feat     = (const float*)d_in[0];
    const float* edge_w   = (const float*)d_in[1];
    const float* weight   = (const float*)d_in[2];
    const float* bias     = (const float*)d_in[3];
    const int*   edge_src = (const int*)d_in[4];
    const int*   edge_dst = (const int*)d_in[5];
    float* out = (float*)d_out;

    init_kernel<<<(N_NODES * OUT_F / 4 + 255) / 256, 256>>>((float4*)out, weight);
    gemm_bf16_kernel<<<(N_NODES + 127) / 128, 256>>>(feat);
    edge_kernel<<<(int)(((long long)QRT_E * 16 + 255) / 256), 256>>>(edge_src, edge_dst, edge_w, out);
    finalize_kernel<<<(N_NODES * OUT_F / 4 + 255) / 256, 256>>>((float4*)out, bias);
}